// round 16
// baseline (speedup 1.0000x reference)
#include <cuda_runtime.h>
#include <stdint.h>

#define NPART_MAX 100000
#define CUTOFF 0.9f
#define PREFAC 138.93544539709032f

#define NBINS 32
#define BIN_W_MAX 3125                        // ceil(100000/32)
#define K1_THREADS 256
#define K1_BLOCKS 592
#define K1_WARPS 8
#define NWT (K1_BLOCKS * K1_WARPS)            // 4736 warps
#define WCAP 256                              // per-(warp,bin) region words; mean ~106, 15 sigma
#define BUF 40                                // smem buffer words per (warp,bin); max transient 39
#define BLOCKS_PER_BIN 74
#define K2_BLOCKS (NBINS * BLOCKS_PER_BIN)    // 2368
#define WG_PER_BLOCK (NWT / BLOCKS_PER_BIN)   // 64 exact

__device__ float4 g_pos[NPART_MAX];           // {x,y,z, q*sqrt(PREFAC)}
__device__ float2 g_sig[NPART_MAX];           // {sigma, epsilon}
__device__ unsigned g_binned[(size_t)NBINS * NWT * WCAP];  // (j<<12 | i_local)
__device__ unsigned g_wcounts[(size_t)NWT * NBINS];

// ---------------------------------------------------------------------------
__device__ __forceinline__ float pair_energy_direct(int i, int j,
                                                    float Lx, float Ly, float Lz,
                                                    float iLx, float iLy, float iLz,
                                                    float cut2)
{
    float4 a = g_pos[i];
    float4 b = g_pos[j];
    float dx = a.x - b.x, dy = a.y - b.y, dz = a.z - b.z;
    dx -= Lx * rintf(dx * iLx);
    dy -= Ly * rintf(dy * iLy);
    dz -= Lz * rintf(dz * iLz);
    float r2 = dx * dx + dy * dy + dz * dz;
    if (r2 < cut2 && (i / 3 != j / 3)) {
        float2 sa = g_sig[i];
        float2 sb = g_sig[j];
        float inv_r = rsqrtf(r2);
        float inv_r2 = inv_r * inv_r;
        float e_coul = a.w * b.w * inv_r;
        float sig = 0.5f * (sa.x + sb.x);
        float eps = sqrtf(sa.y * sb.y);
        float sr2 = sig * sig * inv_r2;
        float sr6 = sr2 * sr2 * sr2;
        return e_coul + 4.0f * eps * (sr6 * sr6 - sr6);
    }
    return 0.0f;
}

// ---------------------------------------------------------------------------
__global__ void pack_kernel(const float* __restrict__ coords,
                            const float* __restrict__ charges,
                            const float* __restrict__ sigma,
                            const float* __restrict__ epsilon,
                            float* __restrict__ out, int n)
{
    int i = blockIdx.x * blockDim.x + threadIdx.x;
    if (i == 0) out[0] = 0.0f;                // d_out poisoned; zero it
    if (i < n) {
        g_pos[i] = make_float4(coords[3*i], coords[3*i+1], coords[3*i+2],
                               charges[i] * sqrtf(PREFAC));
        g_sig[i] = make_float2(sigma[i], epsilon[i]);
    }
}

// ---------------------------------------------------------------------------
// K1: bin pairs by i. smem-staged: per-warp per-bin buffers, coalesced 32-128B
// chunk flushes to per-(warp,bin) global regions. No atomics, no IDIV.
__global__ void __launch_bounds__(K1_THREADS)
partition_kernel(const int2* __restrict__ pairs, int npairs, int bin_w,
                 unsigned rcp, const float* __restrict__ box,
                 float* __restrict__ out)
{
    __shared__ unsigned s_buf[K1_WARPS][NBINS][BUF];  // 40 KB
    __shared__ int s_cnt[K1_WARPS][NBINS + 1];        // +1 sentinel for invalid lanes
    __shared__ int s_cur[K1_WARPS][NBINS];

    int lane = threadIdx.x & 31;
    int w    = threadIdx.x >> 5;
    int wgid = blockIdx.x * K1_WARPS + w;

    if (lane <= NBINS) s_cnt[w][lane] = 0;
    if (lane <  NBINS) s_cur[w][lane] = 0;
    __syncwarp();

    float Lx = __ldg(&box[0]), Ly = __ldg(&box[4]), Lz = __ldg(&box[8]);
    float iLx = __frcp_rn(Lx), iLy = __frcp_rn(Ly), iLz = __frcp_rn(Lz);
    const float cut2 = CUTOFF * CUTOFF;
    float ovf = 0.0f;

    int ppw   = (npairs + NWT - 1) / NWT;
    int start = wgid * ppw;
    int end   = start + ppw;
    if (end > npairs) end = npairs;

    const unsigned FULL = 0xffffffffu;
    const unsigned lmask = (lane == 0) ? 0u : (FULL >> (32 - lane));

    for (int base = start; base < end; base += 32) {
        int idx    = base + lane;
        bool valid = idx < end;
        int2 p = valid ? __ldcs(&pairs[idx]) : make_int2(0, 0);
        int bin = valid ? (int)__umulhi((unsigned)p.x, rcp) : NBINS;  // exact i/bin_w
        unsigned word = ((unsigned)p.y << 12) | (unsigned)(p.x - bin * bin_w);

        unsigned m = __match_any_sync(FULL, bin);
        int rank  = __popc(m & lmask);
        int grp   = __popc(m);
        int cbase = s_cnt[w][bin];
        __syncwarp();
        if (rank == 0) s_cnt[w][bin] = cbase + grp;   // leaders, distinct bins
        __syncwarp();
        if (valid && bin < NBINS) s_buf[w][bin][cbase + rank] = word;  // slot <= 38 < BUF
        __syncwarp();                                  // STS visible to flush reads

        bool need = (rank == 0) && (bin < NBINS) && (cbase + grp >= 8);
        unsigned fb = __ballot_sync(FULL, need);
        while (fb) {
            int sl = __ffs(fb) - 1; fb &= fb - 1;
            int fbin = __shfl_sync(FULL, bin, sl);
            int fcnt = s_cnt[w][fbin];
            int f = fcnt & ~7; if (f > 32) f = 32;     // flush 8..32 words, leaves <8 or cnt-32
            int cur = s_cur[w][fbin];
            unsigned myw = (lane < f) ? s_buf[w][fbin][lane] : 0u;
            if (cur + f <= WCAP) {
                if (lane < f)                           // coalesced 32-128B burst
                    g_binned[((size_t)fbin * NWT + wgid) * WCAP + cur + lane] = myw;
            } else {                                    // ~impossible; compute in place
                if (lane < f) {
                    int ii = fbin * bin_w + (int)(myw & 4095u);
                    int jj = (int)(myw >> 12);
                    ovf += pair_energy_direct(ii, jj, Lx, Ly, Lz, iLx, iLy, iLz, cut2);
                }
            }
            int rem = fcnt - f;                         // <= 7
            unsigned t = (lane < rem) ? s_buf[w][fbin][f + lane] : 0u;
            __syncwarp();
            if (lane < rem) s_buf[w][fbin][lane] = t;
            if (lane == 0) {
                s_cnt[w][fbin] = rem;
                if (cur + f <= WCAP) s_cur[w][fbin] = cur + f;
            }
            __syncwarp();
        }
    }

    __syncwarp();
    // drain remainders (<8 words per bin) + publish counts
    for (int b = 0; b < NBINS; ++b) {
        int c   = s_cnt[w][b];
        int cur = s_cur[w][b];
        if (c > 0) {
            if (cur + c <= WCAP) {
                if (lane < c)
                    g_binned[((size_t)b * NWT + wgid) * WCAP + cur + lane] = s_buf[w][b][lane];
                cur += c;
            } else {
                if (lane < c) {
                    unsigned myw = s_buf[w][b][lane];
                    int ii = b * bin_w + (int)(myw & 4095u);
                    int jj = (int)(myw >> 12);
                    ovf += pair_energy_direct(ii, jj, Lx, Ly, Lz, iLx, iLy, iLz, cut2);
                }
            }
        }
        if (lane == 0) g_wcounts[(size_t)wgid * NBINS + b] = (unsigned)cur;
    }

    #pragma unroll
    for (int off = 16; off > 0; off >>= 1)
        ovf += __shfl_xor_sync(FULL, ovf, off);
    if (lane == 0 && ovf != 0.0f) atomicAdd(out, ovf);
}

// ---------------------------------------------------------------------------
// K2: per-bin energy. i-gather from 50KB smem slice; only j-gather hits L1tex.
__global__ void __launch_bounds__(256)
energy2_kernel(const float* __restrict__ box, float* __restrict__ out,
               int n, int bin_w)
{
    __shared__ float4 s_pos[BIN_W_MAX];

    int bin   = blockIdx.x / BLOCKS_PER_BIN;
    int chunk = blockIdx.x % BLOCKS_PER_BIN;
    int ibase = bin * bin_w;

    int nslice = n - ibase;
    if (nslice > bin_w) nslice = bin_w;
    if (nslice < 0) nslice = 0;
    for (int t = threadIdx.x; t < nslice; t += 256)
        s_pos[t] = g_pos[ibase + t];
    __syncthreads();

    float Lx = __ldg(&box[0]), Ly = __ldg(&box[4]), Lz = __ldg(&box[8]);
    float iLx = __frcp_rn(Lx), iLy = __frcp_rn(Ly), iLz = __frcp_rn(Lz);
    const float cut2 = CUTOFF * CUTOFF;

    float acc = 0.0f;
    int lane = threadIdx.x & 31;
    int w    = threadIdx.x >> 5;
    int wg0  = chunk * WG_PER_BLOCK;

    for (int wi = w; wi < WG_PER_BLOCK; wi += 8) {
        int wg  = wg0 + wi;
        int cnt = (int)g_wcounts[(size_t)wg * NBINS + bin];
        const unsigned* src = &g_binned[((size_t)bin * NWT + wg) * WCAP];
        for (int s = lane; s < cnt; s += 32) {
            unsigned word = __ldcs(&src[s]);
            int il = (int)(word & 4095u);
            int j  = (int)(word >> 12);
            float4 a = s_pos[il];                 // smem
            float4 b = g_pos[j];                  // the remaining gather wavefront

            float dx = a.x - b.x, dy = a.y - b.y, dz = a.z - b.z;
            dx -= Lx * rintf(dx * iLx);
            dy -= Ly * rintf(dy * iLy);
            dz -= Lz * rintf(dz * iLz);
            float r2 = dx * dx + dy * dy + dz * dz;

            int i = ibase + il;
            if (r2 < cut2 && (i / 3 != j / 3)) {  // ~0.3% taken
                float2 sa = g_sig[i];
                float2 sb = g_sig[j];
                float inv_r  = rsqrtf(r2);
                float inv_r2 = inv_r * inv_r;
                float e_coul = a.w * b.w * inv_r;
                float sig = 0.5f * (sa.x + sb.x);
                float eps = sqrtf(sa.y * sb.y);
                float sr2 = sig * sig * inv_r2;
                float sr6 = sr2 * sr2 * sr2;
                acc += e_coul + 4.0f * eps * (sr6 * sr6 - sr6);
            }
        }
    }

    #pragma unroll
    for (int off = 16; off > 0; off >>= 1)
        acc += __shfl_xor_sync(0xFFFFFFFFu, acc, off);

    __shared__ float warp_sums[8];
    if (lane == 0) warp_sums[w] = acc;
    __syncthreads();
    if (w == 0) {
        float v = (lane < 8) ? warp_sums[lane] : 0.0f;
        #pragma unroll
        for (int off = 4; off > 0; off >>= 1)
            v += __shfl_xor_sync(0xFFFFFFFFu, v, off);
        if (lane == 0) atomicAdd(out, v);
    }
}

// ---------------------------------------------------------------------------
extern "C" void kernel_launch(void* const* d_in, const int* in_sizes, int n_in,
                              void* d_out, int out_size)
{
    const float* coords  = (const float*)d_in[0];
    const float* box     = (const float*)d_in[1];
    const float* charges = (const float*)d_in[2];
    const float* sigma   = (const float*)d_in[3];
    const float* epsilon = (const float*)d_in[4];
    const int*   pairs   = (const int*)d_in[5];

    int n      = in_sizes[2];
    int npairs = in_sizes[5] / 2;
    int bin_w  = (n + NBINS - 1) / NBINS;     // 3125 for n=100000
    // magic reciprocal for exact i/bin_w on device (valid: i < 2^32/bin_w)
    unsigned rcp = (unsigned)(((1ULL << 32) + (unsigned)bin_w - 1) / (unsigned)bin_w);

    float* out = (float*)d_out;

    pack_kernel<<<(n + 255) / 256, 256>>>(coords, charges, sigma, epsilon, out, n);
    partition_kernel<<<K1_BLOCKS, K1_THREADS>>>((const int2*)pairs, npairs, bin_w,
                                                rcp, box, out);
    energy2_kernel<<<K2_BLOCKS, 256>>>(box, out, n, bin_w);
}